// round 14
// baseline (speedup 1.0000x reference)
#include <cuda_runtime.h>
#include <cstdint>
#include <math.h>

#define Sx 512
#define Bx 64
#define Hx 256
#define Lx 6
#define G3 768          // 3*H
#define DHx 512         // 2*H
#define M_TOT (Sx*Bx)   // 32768

typedef unsigned long long ull;

// ---------------- device scratch (static: no allocation allowed) ----------------
__device__ float g_gxT[2][(size_t)Sx*G3*Bx];   // [dir][s][gate*256+j][b] (bias added)
__device__ float g_io[(size_t)Sx*Bx*DHx];      // layer input/output (S,B,2H)

__device__ __forceinline__ unsigned f2tf32(float f){
    unsigned u;
    asm("cvt.rna.tf32.f32 %0,%1;" : "=r"(u) : "f"(f));
    return u;
}
__device__ __forceinline__ unsigned ctarank(){
    unsigned r; asm("mov.u32 %0, %%cluster_ctarank;" : "=r"(r)); return r;
}

// =================================================================================
// gate_x GEMM, tf32 tensor cores (proven R8): block 128x128, BK=16, 8 warps,
// warp tile 64x32. Writes transposed gxT with bias added.
// =================================================================================
template<int K>
__global__ void __launch_bounds__(256,2) gatex_gemm(
    const float* __restrict__ xin,
    const float* __restrict__ Wbase,   // [2][768][K]
    const float* __restrict__ bias)    // [2][768]
{
    __shared__ unsigned As[16][136];
    __shared__ unsigned Bs[16][136];

    const int dir = blockIdx.z;
    const float* A = (K == 128) ? xin : g_io;
    const float* W = Wbase + (size_t)dir * G3 * K;
    const int n0 = blockIdx.x * 128;
    const int m0 = blockIdx.y * 128;
    const int tid = threadIdx.x;
    const int row  = tid >> 1;
    const int part = tid & 1;
    const int lane = tid & 31;
    const int w    = tid >> 5;
    const int wm = (w & 1) * 64;
    const int wn = (w >> 1) * 32;
    const int g = lane >> 2;
    const int t = lane & 3;

    float acc[4][4][4];
    #pragma unroll
    for (int mt = 0; mt < 4; mt++)
        #pragma unroll
        for (int nt = 0; nt < 4; nt++)
            #pragma unroll
            for (int i = 0; i < 4; i++) acc[mt][nt][i] = 0.f;

    const float* Ald = A + (size_t)(m0 + row) * K + part * 4;
    const float* Wld = W + (size_t)(n0 + row) * K + part * 4;

    float4 av0 = *(const float4*)(Ald);
    float4 av1 = *(const float4*)(Ald + 8);
    float4 wv0 = *(const float4*)(Wld);
    float4 wv1 = *(const float4*)(Wld + 8);

    for (int kt = 0; kt < K; kt += 16){
        const int k0 = part * 4;
        As[k0+0][row] = f2tf32(av0.x); As[k0+1][row] = f2tf32(av0.y);
        As[k0+2][row] = f2tf32(av0.z); As[k0+3][row] = f2tf32(av0.w);
        As[k0+8][row] = f2tf32(av1.x); As[k0+9][row] = f2tf32(av1.y);
        As[k0+10][row] = f2tf32(av1.z); As[k0+11][row] = f2tf32(av1.w);
        Bs[k0+0][row] = f2tf32(wv0.x); Bs[k0+1][row] = f2tf32(wv0.y);
        Bs[k0+2][row] = f2tf32(wv0.z); Bs[k0+3][row] = f2tf32(wv0.w);
        Bs[k0+8][row] = f2tf32(wv1.x); Bs[k0+9][row] = f2tf32(wv1.y);
        Bs[k0+10][row] = f2tf32(wv1.z); Bs[k0+11][row] = f2tf32(wv1.w);
        __syncthreads();
        if (kt + 16 < K){
            av0 = *(const float4*)(Ald + kt + 16);
            av1 = *(const float4*)(Ald + kt + 24);
            wv0 = *(const float4*)(Wld + kt + 16);
            wv1 = *(const float4*)(Wld + kt + 24);
        }
        #pragma unroll
        for (int c = 0; c < 2; c++){
            unsigned af[4][4], bf[4][2];
            #pragma unroll
            for (int mt = 0; mt < 4; mt++){
                const int m = wm + mt*16 + g;
                af[mt][0] = As[c*8 + t][m];
                af[mt][1] = As[c*8 + t][m + 8];
                af[mt][2] = As[c*8 + t + 4][m];
                af[mt][3] = As[c*8 + t + 4][m + 8];
            }
            #pragma unroll
            for (int nt = 0; nt < 4; nt++){
                const int n = wn + nt*8 + g;
                bf[nt][0] = Bs[c*8 + t][n];
                bf[nt][1] = Bs[c*8 + t + 4][n];
            }
            #pragma unroll
            for (int mt = 0; mt < 4; mt++)
                #pragma unroll
                for (int nt = 0; nt < 4; nt++)
                    asm volatile(
                        "mma.sync.aligned.m16n8k8.row.col.f32.tf32.tf32.f32 "
                        "{%0,%1,%2,%3},{%4,%5,%6,%7},{%8,%9},{%0,%1,%2,%3};"
                        : "+f"(acc[mt][nt][0]), "+f"(acc[mt][nt][1]),
                          "+f"(acc[mt][nt][2]), "+f"(acc[mt][nt][3])
                        : "r"(af[mt][0]), "r"(af[mt][1]), "r"(af[mt][2]), "r"(af[mt][3]),
                          "r"(bf[nt][0]), "r"(bf[nt][1]));
        }
        __syncthreads();
    }

    float* out = g_gxT[dir];
    const float* bs = bias + dir * G3;
    #pragma unroll
    for (int mt = 0; mt < 4; mt++){
        #pragma unroll
        for (int nt = 0; nt < 4; nt++){
            const int mr = m0 + wm + mt*16 + g;
            const int nc = n0 + wn + nt*8 + 2*t;
            const float b0 = bs[nc], b1 = bs[nc + 1];
            {
                const int s = mr >> 6, b = mr & 63;
                out[((size_t)s*G3 + nc    )*Bx + b] = acc[mt][nt][0] + b0;
                out[((size_t)s*G3 + nc + 1)*Bx + b] = acc[mt][nt][1] + b1;
            }
            {
                const int m2 = mr + 8;
                const int s = m2 >> 6, b = m2 & 63;
                out[((size_t)s*G3 + nc    )*Bx + b] = acc[mt][nt][2] + b0;
                out[((size_t)s*G3 + nc + 1)*Bx + b] = acc[mt][nt][3] + b1;
            }
        }
    }
}

// =================================================================================
// Cluster GRU layer (R13 + mbarrier sync): grid 128 = 32 clusters x 4 CTAs, 384 thr.
// Per-CTA smem mbarrier (expected 48 = 12 warps x 4 CTAs, elected-lane arrive).
// Epilogue threads push their own hnew to 3 remote ranks, __syncwarp, elected
// arrive.release.cluster on all 4 ranks. Compute-only warps arrive after the
// reduction barrier (reads done). Next step: parity try_wait (~90-150 cyc).
// =================================================================================
#define WS_BYTES (96*129*16)                 // 198,144
#define HS_BYTES 4096
#define RED_OFF  (WS_BYTES + 2*HS_BYTES)     // 206,336
#define MBAR_OFF (RED_OFF + 12288)           // 218,624
#define SMEM_GRU (MBAR_OFF + 64)

#define MBAR_ARRIVE_RK(off, rk)                                         \
    asm volatile("{\n\t.reg .b32 ra;\n\t"                               \
        "mapa.shared::cluster.u32 ra, %0, %1;\n\t"                      \
        "mbarrier.arrive.release.cluster.shared::cluster.b64 _, [ra];\n\t}" \
        :: "r"(off), "r"(rk) : "memory")

#define MBAR_WAIT(off, par) do {                                        \
    unsigned _d;                                                        \
    do {                                                                \
        asm volatile("{\n\t.reg .pred p;\n\t"                           \
            "mbarrier.try_wait.parity.acquire.cluster.shared::cta.b64 p, [%1], %2, 0x989680;\n\t" \
            "selp.b32 %0,1,0,p;\n\t}"                                   \
            : "=r"(_d) : "r"(off), "r"(par) : "memory");                \
    } while (!_d);                                                      \
} while (0)

__global__ void __launch_bounds__(384,1) __cluster_dims__(4,1,1)
gru_layer(
    const float* __restrict__ h0_l,    // [2][B][H]
    const float* __restrict__ whh_l,   // [2][768][256]
    const float* __restrict__ bhh_l,   // [2][768]
    float* __restrict__ hn_out)        // [2][B][H] slice of d_out
{
    extern __shared__ __align__(16) float smem[];
    const unsigned sb = (unsigned)__cvta_generic_to_shared(smem);
    const unsigned mb = sb + MBAR_OFF;

    const int cid  = blockIdx.x >> 2;   // cluster id 0..31
    const int q    = (int)ctarank();    // j-quarter 0..3
    const int dir  = cid >> 4;
    const int bgrp = cid & 15;
    const int tid  = threadIdx.x;

    // compute-phase mapping
    const int ks   = tid / 96;          // 0..3 (k-quarter)
    const int rem  = tid - ks*96;
    const int gate = rem >> 5;          // 0..2
    const int jl2  = rem & 31;          // j-pair index

    // epilogue mapping (tid<256)
    const int jl = tid >> 2;            // 0..63
    const int b  = tid & 3;
    const int jglob = q*64 + jl;
    const int bglob = bgrp*4 + b;

    // ---- stage W interleaved: ws[(gate*32+jl2)*129 + k2][4] = {j0e0,j0e1,j1e0,j1e1}
    for (int i = tid; i < 49152; i += 384){
        const int f = i & 3, jsel = f >> 1, e = f & 1;
        const int k2 = (i >> 2) & 127;
        const int rw = i >> 9;                 // 0..95
        const int gg = rw >> 5, jj2 = rw & 31;
        const int jloc = 2*jj2 + jsel;
        smem[((gg*32 + jj2)*129 + k2)*4 + f] =
            whh_l[((size_t)dir*G3 + gg*Hx + q*64 + jloc)*Hx + 2*k2 + e];
    }

    // ---- stage h0 into hsA: [k2][b][e], full 256 j, own 4 batches
    float* hsA = smem + WS_BYTES/4;
    for (int i = tid; i < 1024; i += 384){
        const int j = i >> 2, bb = i & 3;
        hsA[(j >> 1)*8 + bb*2 + (j & 1)] =
            h0_l[(size_t)dir*Bx*Hx + (size_t)(bgrp*4 + bb)*Hx + j];
    }

    // epilogue biases
    float br = 0.f, bz = 0.f, bn = 0.f;
    if (tid < 256){
        br = bhh_l[dir*G3 + jglob];
        bz = bhh_l[dir*G3 + Hx + jglob];
        bn = bhh_l[dir*G3 + 2*Hx + jglob];
    }

    // init mbarrier (expected 48 arrivals/phase: 12 warps x 4 CTAs)
    if (tid == 0)
        asm volatile("mbarrier.init.shared.b64 [%0], 48;" :: "r"(mb) : "memory");
    __syncthreads();
    // one-time cluster sync: mbar inits + W/h0 staging visible before any arrive
    asm volatile("barrier.cluster.arrive.aligned;" ::: "memory");
    asm volatile("barrier.cluster.wait.aligned;" ::: "memory");

    const unsigned wadr = sb + (unsigned)(((gate*32 + jl2)*129 + ks*32)*16);
    float* redp = smem + RED_OFF/4;
    const float* gxb = g_gxT[dir];
    const int hEidx = (jglob >> 1)*8 + b*2 + (jglob & 1);

    int cur = 0;
    for (int t = 0; t < Sx; t++){
        const int ta = dir ? (Sx - 1 - t) : t;
        const unsigned hsC_u = sb + WS_BYTES + (unsigned)cur*HS_BYTES;
        const unsigned hsN_u = sb + WS_BYTES + (unsigned)(cur ^ 1)*HS_BYTES;

        // ---- prefetch gate_x (independent of h); overlaps the wait
        float xr = 0.f, xz = 0.f, xn = 0.f;
        if (tid < 256){
            const float* p = gxb + (size_t)ta*G3*Bx + bglob;
            xr = __ldg(p + (size_t)(0*Hx + jglob)*Bx);
            xz = __ldg(p + (size_t)(1*Hx + jglob)*Bx);
            xn = __ldg(p + (size_t)(2*Hx + jglob)*Bx);
        }

        // ---- wait for previous step's arrivals (parity = (t-1)&1)
        if (t > 0)
            MBAR_WAIT(mb, (unsigned)((t - 1) & 1));

        float hprev = 0.f;
        if (tid < 256)
            asm volatile("ld.shared.f32 %0,[%1];"
                         : "=f"(hprev) : "r"(hsC_u + (unsigned)(hEidx*4)));

        // ---- compute: 32 k2-iters, 2 j x 4 b x 3-gate-split
        ull aJ0B0=0, aJ0B1=0, aJ0B2=0, aJ0B3=0, aJ1B0=0, aJ1B1=0, aJ1B2=0, aJ1B3=0;
        const unsigned hbase = hsC_u + (unsigned)(ks*32*32);
        #pragma unroll 8
        for (int k = 0; k < 32; k++){
            ull wj0, wj1, hb0, hb1, hb2, hb3;
            asm volatile("ld.shared.v2.u64 {%0,%1},[%2];"
                         : "=l"(wj0), "=l"(wj1) : "r"(wadr + k*16));
            asm volatile("ld.shared.v2.u64 {%0,%1},[%2];"
                         : "=l"(hb0), "=l"(hb1) : "r"(hbase + k*32));
            asm volatile("ld.shared.v2.u64 {%0,%1},[%2];"
                         : "=l"(hb2), "=l"(hb3) : "r"(hbase + k*32 + 16));
            asm("fma.rn.f32x2 %0,%1,%2,%0;" : "+l"(aJ0B0) : "l"(wj0), "l"(hb0));
            asm("fma.rn.f32x2 %0,%1,%2,%0;" : "+l"(aJ0B1) : "l"(wj0), "l"(hb1));
            asm("fma.rn.f32x2 %0,%1,%2,%0;" : "+l"(aJ0B2) : "l"(wj0), "l"(hb2));
            asm("fma.rn.f32x2 %0,%1,%2,%0;" : "+l"(aJ0B3) : "l"(wj0), "l"(hb3));
            asm("fma.rn.f32x2 %0,%1,%2,%0;" : "+l"(aJ1B0) : "l"(wj1), "l"(hb0));
            asm("fma.rn.f32x2 %0,%1,%2,%0;" : "+l"(aJ1B1) : "l"(wj1), "l"(hb1));
            asm("fma.rn.f32x2 %0,%1,%2,%0;" : "+l"(aJ1B2) : "l"(wj1), "l"(hb2));
            asm("fma.rn.f32x2 %0,%1,%2,%0;" : "+l"(aJ1B3) : "l"(wj1), "l"(hb3));
        }
        // collapse k-parity, publish partials: red[(ks*3+gate)*64 + j][b]
        {
            float4 v0, v1; float lo, hi;
            asm("mov.b64 {%0,%1},%2;" : "=f"(lo), "=f"(hi) : "l"(aJ0B0)); v0.x = lo + hi;
            asm("mov.b64 {%0,%1},%2;" : "=f"(lo), "=f"(hi) : "l"(aJ0B1)); v0.y = lo + hi;
            asm("mov.b64 {%0,%1},%2;" : "=f"(lo), "=f"(hi) : "l"(aJ0B2)); v0.z = lo + hi;
            asm("mov.b64 {%0,%1},%2;" : "=f"(lo), "=f"(hi) : "l"(aJ0B3)); v0.w = lo + hi;
            asm("mov.b64 {%0,%1},%2;" : "=f"(lo), "=f"(hi) : "l"(aJ1B0)); v1.x = lo + hi;
            asm("mov.b64 {%0,%1},%2;" : "=f"(lo), "=f"(hi) : "l"(aJ1B1)); v1.y = lo + hi;
            asm("mov.b64 {%0,%1},%2;" : "=f"(lo), "=f"(hi) : "l"(aJ1B2)); v1.z = lo + hi;
            asm("mov.b64 {%0,%1},%2;" : "=f"(lo), "=f"(hi) : "l"(aJ1B3)); v1.w = lo + hi;
            float4* rp = (float4*)(redp + ((ks*3 + gate)*64 + 2*jl2)*4);
            rp[0] = v0;
            rp[1] = v1;
        }
        __syncthreads();

        // ---- compute-only warps: hsC reads done -> arrive now
        if (tid >= 256){
            if (t < Sx - 1 && (tid & 31) == 0){
                MBAR_ARRIVE_RK(mb, 0);
                MBAR_ARRIVE_RK(mb, 1);
                MBAR_ARRIVE_RK(mb, 2);
                MBAR_ARRIVE_RK(mb, 3);
            }
        } else {
            // ---- epilogue: thread = (jl, b); push OWN hnew to all 4 ranks
            float sr = 0.f, sz = 0.f, sn = 0.f;
            #pragma unroll
            for (int kq = 0; kq < 4; kq++){
                sr += redp[((kq*3 + 0)*64 + jl)*4 + b];
                sz += redp[((kq*3 + 1)*64 + jl)*4 + b];
                sn += redp[((kq*3 + 2)*64 + jl)*4 + b];
            }
            const float r = __fdividef(1.f, 1.f + __expf(-(xr + sr + br)));
            const float z = __fdividef(1.f, 1.f + __expf(-(xz + sz + bz)));
            const float targ = xn + r * (sn + bn);
            const float nn = 1.f - __fdividef(2.f, __expf(2.f*targ) + 1.f);
            const float hnew = (1.f - z) * nn + z * hprev;

            const unsigned off = hsN_u + (unsigned)(hEidx*4);
            if (t < Sx - 1){
                asm volatile("st.shared.f32 [%0],%1;" :: "r"(off), "f"(hnew) : "memory");
                #pragma unroll
                for (int rk = 1; rk < 4; rk++){
                    const int rr = (q + rk) & 3;
                    asm volatile(
                        "{\n\t.reg .b32 ra;\n\t"
                        "mapa.shared::cluster.u32 ra, %0, %1;\n\t"
                        "st.shared::cluster.f32 [ra], %2;\n\t}"
                        :: "r"(off), "r"(rr), "f"(hnew) : "memory");
                }
            }
            g_io[((size_t)ta*Bx + bglob)*DHx + dir*Hx + jglob] = hnew;
            if (t == Sx - 1)
                hn_out[(size_t)dir*Bx*Hx + (size_t)bglob*Hx + jglob] = hnew;

            if (t < Sx - 1){
                __syncwarp();
                if ((tid & 31) == 0){
                    MBAR_ARRIVE_RK(mb, 0);
                    MBAR_ARRIVE_RK(mb, 1);
                    MBAR_ARRIVE_RK(mb, 2);
                    MBAR_ARRIVE_RK(mb, 3);
                }
            }
        }
        cur ^= 1;
    }
}

// =================================================================================
extern "C" void kernel_launch(void* const* d_in, const int* in_sizes, int n_in,
                              void* d_out, int out_size)
{
    const float* x     = (const float*)d_in[0];   // (512,64,128)
    const float* h0    = (const float*)d_in[1];   // (12,64,256)
    const float* w_ih0 = (const float*)d_in[2];   // (2,768,128)
    const float* w_ih  = (const float*)d_in[3];   // (5,2,768,512)
    const float* w_hh  = (const float*)d_in[4];   // (6,2,768,256)
    const float* b_ih  = (const float*)d_in[5];   // (6,2,768)
    const float* b_hh  = (const float*)d_in[6];   // (6,2,768)
    float* out = (float*)d_out;                   // (12,64,256)

    cudaFuncSetAttribute(gru_layer, cudaFuncAttributeMaxDynamicSharedMemorySize, SMEM_GRU);

    for (int layer = 0; layer < Lx; layer++){
        dim3 gg(G3/128, M_TOT/128, 2);
        if (layer == 0){
            gatex_gemm<128><<<gg, 256>>>(x, w_ih0, b_ih);
        } else {
            gatex_gemm<512><<<gg, 256>>>(
                x,
                w_ih + (size_t)(layer-1) * 2 * G3 * 512,
                b_ih + (size_t)layer * 2 * G3);
        }
        gru_layer<<<128, 384, SMEM_GRU>>>(
            h0   + (size_t)layer * 2 * Bx * Hx,
            w_hh + (size_t)layer * 2 * G3 * Hx,
            b_hh + (size_t)layer * 2 * G3,
            out  + (size_t)layer * 2 * Bx * Hx);
    }
}

// round 15
// speedup vs baseline: 1.1920x; 1.1920x over previous
#include <cuda_runtime.h>
#include <cstdint>
#include <math.h>

#define Sx 512
#define Bx 64
#define Hx 256
#define Lx 6
#define G3 768          // 3*H
#define DHx 512         // 2*H
#define M_TOT (Sx*Bx)   // 32768

typedef unsigned long long ull;

// ---------------- device scratch (static: no allocation allowed) ----------------
__device__ float g_gxT[2][(size_t)Sx*G3*Bx];   // [dir][s][gate*256+j][b] (bias added)
__device__ float g_io[(size_t)Sx*Bx*DHx];      // layer input/output (S,B,2H)

__device__ __forceinline__ unsigned f2tf32(float f){
    unsigned u;
    asm("cvt.rna.tf32.f32 %0,%1;" : "=r"(u) : "f"(f));
    return u;
}
__device__ __forceinline__ unsigned ctarank(){
    unsigned r; asm("mov.u32 %0, %%cluster_ctarank;" : "=r"(r)); return r;
}

// =================================================================================
// gate_x GEMM, tf32 tensor cores: block 128x128, BK=16, 8 warps, warp tile 64x32.
// DEPTH-2 register pipeline: global loads issued two compute-phases ahead.
// Writes transposed gxT with bias added.
// =================================================================================
template<int K>
__global__ void __launch_bounds__(256,2) gatex_gemm(
    const float* __restrict__ xin,
    const float* __restrict__ Wbase,   // [2][768][K]
    const float* __restrict__ bias)    // [2][768]
{
    __shared__ unsigned As[16][136];
    __shared__ unsigned Bs[16][136];

    const int dir = blockIdx.z;
    const float* A = (K == 128) ? xin : g_io;
    const float* W = Wbase + (size_t)dir * G3 * K;
    const int n0 = blockIdx.x * 128;
    const int m0 = blockIdx.y * 128;
    const int tid = threadIdx.x;
    const int row  = tid >> 1;
    const int part = tid & 1;
    const int lane = tid & 31;
    const int w    = tid >> 5;
    const int wm = (w & 1) * 64;
    const int wn = (w >> 1) * 32;
    const int g = lane >> 2;
    const int t = lane & 3;

    float acc[4][4][4];
    #pragma unroll
    for (int mt = 0; mt < 4; mt++)
        #pragma unroll
        for (int nt = 0; nt < 4; nt++)
            #pragma unroll
            for (int i = 0; i < 4; i++) acc[mt][nt][i] = 0.f;

    const float* Ald = A + (size_t)(m0 + row) * K + part * 4;
    const float* Wld = W + (size_t)(n0 + row) * K + part * 4;

    // depth-2 prefetch: av* = tile to store now, bv* = tile one ahead
    float4 av0 = *(const float4*)(Ald);
    float4 av1 = *(const float4*)(Ald + 8);
    float4 wv0 = *(const float4*)(Wld);
    float4 wv1 = *(const float4*)(Wld + 8);
    float4 bv0, bv1, xw0, xw1;
    if (K > 16){
        bv0 = *(const float4*)(Ald + 16);
        bv1 = *(const float4*)(Ald + 24);
        xw0 = *(const float4*)(Wld + 16);
        xw1 = *(const float4*)(Wld + 24);
    }

    for (int kt = 0; kt < K; kt += 16){
        const int k0 = part * 4;
        As[k0+0][row] = f2tf32(av0.x); As[k0+1][row] = f2tf32(av0.y);
        As[k0+2][row] = f2tf32(av0.z); As[k0+3][row] = f2tf32(av0.w);
        As[k0+8][row] = f2tf32(av1.x); As[k0+9][row] = f2tf32(av1.y);
        As[k0+10][row] = f2tf32(av1.z); As[k0+11][row] = f2tf32(av1.w);
        Bs[k0+0][row] = f2tf32(wv0.x); Bs[k0+1][row] = f2tf32(wv0.y);
        Bs[k0+2][row] = f2tf32(wv0.z); Bs[k0+3][row] = f2tf32(wv0.w);
        Bs[k0+8][row] = f2tf32(wv1.x); Bs[k0+9][row] = f2tf32(wv1.y);
        Bs[k0+10][row] = f2tf32(wv1.z); Bs[k0+11][row] = f2tf32(wv1.w);
        __syncthreads();

        // rotate pipeline: consume bv into av, issue loads 2 tiles ahead
        av0 = bv0; av1 = bv1; wv0 = xw0; wv1 = xw1;
        if (kt + 32 < K){
            bv0 = *(const float4*)(Ald + kt + 32);
            bv1 = *(const float4*)(Ald + kt + 40);
            xw0 = *(const float4*)(Wld + kt + 32);
            xw1 = *(const float4*)(Wld + kt + 40);
        }

        #pragma unroll
        for (int c = 0; c < 2; c++){
            unsigned af[4][4], bf[4][2];
            #pragma unroll
            for (int mt = 0; mt < 4; mt++){
                const int m = wm + mt*16 + g;
                af[mt][0] = As[c*8 + t][m];
                af[mt][1] = As[c*8 + t][m + 8];
                af[mt][2] = As[c*8 + t + 4][m];
                af[mt][3] = As[c*8 + t + 4][m + 8];
            }
            #pragma unroll
            for (int nt = 0; nt < 4; nt++){
                const int n = wn + nt*8 + g;
                bf[nt][0] = Bs[c*8 + t][n];
                bf[nt][1] = Bs[c*8 + t + 4][n];
            }
            #pragma unroll
            for (int mt = 0; mt < 4; mt++)
                #pragma unroll
                for (int nt = 0; nt < 4; nt++)
                    asm volatile(
                        "mma.sync.aligned.m16n8k8.row.col.f32.tf32.tf32.f32 "
                        "{%0,%1,%2,%3},{%4,%5,%6,%7},{%8,%9},{%0,%1,%2,%3};"
                        : "+f"(acc[mt][nt][0]), "+f"(acc[mt][nt][1]),
                          "+f"(acc[mt][nt][2]), "+f"(acc[mt][nt][3])
                        : "r"(af[mt][0]), "r"(af[mt][1]), "r"(af[mt][2]), "r"(af[mt][3]),
                          "r"(bf[nt][0]), "r"(bf[nt][1]));
        }
        __syncthreads();
    }

    float* out = g_gxT[dir];
    const float* bs = bias + dir * G3;
    #pragma unroll
    for (int mt = 0; mt < 4; mt++){
        #pragma unroll
        for (int nt = 0; nt < 4; nt++){
            const int mr = m0 + wm + mt*16 + g;
            const int nc = n0 + wn + nt*8 + 2*t;
            const float b0 = bs[nc], b1 = bs[nc + 1];
            {
                const int s = mr >> 6, b = mr & 63;
                out[((size_t)s*G3 + nc    )*Bx + b] = acc[mt][nt][0] + b0;
                out[((size_t)s*G3 + nc + 1)*Bx + b] = acc[mt][nt][1] + b1;
            }
            {
                const int m2 = mr + 8;
                const int s = m2 >> 6, b = m2 & 63;
                out[((size_t)s*G3 + nc    )*Bx + b] = acc[mt][nt][2] + b0;
                out[((size_t)s*G3 + nc + 1)*Bx + b] = acc[mt][nt][3] + b1;
            }
        }
    }
}

// =================================================================================
// Cluster GRU layer (EXACT R13, proven 1.42ms/layer): grid 128 = 32 clusters x 4
// CTAs, 384 threads. cluster.sync per step; vectorized DSMEM push; early gx
// prefetch; split arrive/wait.
// =================================================================================
#define WS_BYTES (96*129*16)                 // 198,144
#define HS_BYTES 4096
#define RED_OFF  (WS_BYTES + 2*HS_BYTES)     // 206,336
#define SMEM_GRU (RED_OFF + 12288)           // 218,624

__global__ void __launch_bounds__(384,1) __cluster_dims__(4,1,1)
gru_layer(
    const float* __restrict__ h0_l,    // [2][B][H]
    const float* __restrict__ whh_l,   // [2][768][256]
    const float* __restrict__ bhh_l,   // [2][768]
    float* __restrict__ hn_out)        // [2][B][H] slice of d_out
{
    extern __shared__ __align__(16) float smem[];
    const unsigned sb = (unsigned)__cvta_generic_to_shared(smem);

    const int cid  = blockIdx.x >> 2;   // cluster id 0..31
    const int q    = (int)ctarank();    // j-quarter 0..3
    const int dir  = cid >> 4;
    const int bgrp = cid & 15;
    const int tid  = threadIdx.x;

    // compute-phase mapping
    const int ks   = tid / 96;          // 0..3 (k-quarter)
    const int rem  = tid - ks*96;
    const int gate = rem >> 5;          // 0..2
    const int jl2  = rem & 31;          // j-pair index

    // epilogue mapping (tid<256)
    const int jl = tid >> 2;            // 0..63
    const int b  = tid & 3;
    const int jglob = q*64 + jl;
    const int bglob = bgrp*4 + b;

    // push mapping (tid<192): 3 remote ranks x 64 16B-chunks of own 1KB region
    const int prk   = (q + 1 + (tid >> 6)) & 3;
    const int pchnk = tid & 63;

    // ---- stage W interleaved: ws[(gate*32+jl2)*129 + k2][4] = {j0e0,j0e1,j1e0,j1e1}
    for (int i = tid; i < 49152; i += 384){
        const int f = i & 3, jsel = f >> 1, e = f & 1;
        const int k2 = (i >> 2) & 127;
        const int rw = i >> 9;                 // 0..95
        const int gg = rw >> 5, jj2 = rw & 31;
        const int jloc = 2*jj2 + jsel;
        smem[((gg*32 + jj2)*129 + k2)*4 + f] =
            whh_l[((size_t)dir*G3 + gg*Hx + q*64 + jloc)*Hx + 2*k2 + e];
    }

    // ---- stage h0 into hsA: [k2][b][e], full 256 j, own 4 batches
    float* hsA = smem + WS_BYTES/4;
    for (int i = tid; i < 1024; i += 384){
        const int j = i >> 2, bb = i & 3;
        hsA[(j >> 1)*8 + bb*2 + (j & 1)] =
            h0_l[(size_t)dir*Bx*Hx + (size_t)(bgrp*4 + bb)*Hx + j];
    }

    // epilogue biases
    float br = 0.f, bz = 0.f, bn = 0.f;
    if (tid < 256){
        br = bhh_l[dir*G3 + jglob];
        bz = bhh_l[dir*G3 + Hx + jglob];
        bn = bhh_l[dir*G3 + 2*Hx + jglob];
    }
    __syncthreads();

    const unsigned wadr = sb + (unsigned)(((gate*32 + jl2)*129 + ks*32)*16);
    float* redp = smem + RED_OFF/4;
    const float* gxb = g_gxT[dir];
    const int hEidx = (jglob >> 1)*8 + b*2 + (jglob & 1);

    int cur = 0;
    for (int t = 0; t < Sx; t++){
        const int ta = dir ? (Sx - 1 - t) : t;
        const unsigned hsC_u = sb + WS_BYTES + (unsigned)cur*HS_BYTES;
        const unsigned hsN_u = sb + WS_BYTES + (unsigned)(cur ^ 1)*HS_BYTES;

        // ---- prefetch gate_x for this step (independent of h); hidden by barrier+compute
        float xr = 0.f, xz = 0.f, xn = 0.f;
        if (tid < 256){
            const float* p = gxb + (size_t)ta*G3*Bx + bglob;
            xr = __ldg(p + (size_t)(0*Hx + jglob)*Bx);
            xz = __ldg(p + (size_t)(1*Hx + jglob)*Bx);
            xn = __ldg(p + (size_t)(2*Hx + jglob)*Bx);
        }

        // ---- wait for previous step's DSMEM pushes (arrive was at end of prev step)
        if (t > 0)
            asm volatile("barrier.cluster.wait.aligned;" ::: "memory");

        float hprev = 0.f;
        if (tid < 256)
            asm volatile("ld.shared.f32 %0,[%1];"
                         : "=f"(hprev) : "r"(hsC_u + (unsigned)(hEidx*4)));

        // ---- compute: 32 k2-iters, 2 j x 4 b x 3-gate-split
        ull aJ0B0=0, aJ0B1=0, aJ0B2=0, aJ0B3=0, aJ1B0=0, aJ1B1=0, aJ1B2=0, aJ1B3=0;
        const unsigned hbase = hsC_u + (unsigned)(ks*32*32);
        #pragma unroll 8
        for (int k = 0; k < 32; k++){
            ull wj0, wj1, hb0, hb1, hb2, hb3;
            asm volatile("ld.shared.v2.u64 {%0,%1},[%2];"
                         : "=l"(wj0), "=l"(wj1) : "r"(wadr + k*16));
            asm volatile("ld.shared.v2.u64 {%0,%1},[%2];"
                         : "=l"(hb0), "=l"(hb1) : "r"(hbase + k*32));
            asm volatile("ld.shared.v2.u64 {%0,%1},[%2];"
                         : "=l"(hb2), "=l"(hb3) : "r"(hbase + k*32 + 16));
            asm("fma.rn.f32x2 %0,%1,%2,%0;" : "+l"(aJ0B0) : "l"(wj0), "l"(hb0));
            asm("fma.rn.f32x2 %0,%1,%2,%0;" : "+l"(aJ0B1) : "l"(wj0), "l"(hb1));
            asm("fma.rn.f32x2 %0,%1,%2,%0;" : "+l"(aJ0B2) : "l"(wj0), "l"(hb2));
            asm("fma.rn.f32x2 %0,%1,%2,%0;" : "+l"(aJ0B3) : "l"(wj0), "l"(hb3));
            asm("fma.rn.f32x2 %0,%1,%2,%0;" : "+l"(aJ1B0) : "l"(wj1), "l"(hb0));
            asm("fma.rn.f32x2 %0,%1,%2,%0;" : "+l"(aJ1B1) : "l"(wj1), "l"(hb1));
            asm("fma.rn.f32x2 %0,%1,%2,%0;" : "+l"(aJ1B2) : "l"(wj1), "l"(hb2));
            asm("fma.rn.f32x2 %0,%1,%2,%0;" : "+l"(aJ1B3) : "l"(wj1), "l"(hb3));
        }
        // collapse k-parity, publish partials: red[(ks*3+gate)*64 + j][b]
        {
            float4 v0, v1; float lo, hi;
            asm("mov.b64 {%0,%1},%2;" : "=f"(lo), "=f"(hi) : "l"(aJ0B0)); v0.x = lo + hi;
            asm("mov.b64 {%0,%1},%2;" : "=f"(lo), "=f"(hi) : "l"(aJ0B1)); v0.y = lo + hi;
            asm("mov.b64 {%0,%1},%2;" : "=f"(lo), "=f"(hi) : "l"(aJ0B2)); v0.z = lo + hi;
            asm("mov.b64 {%0,%1},%2;" : "=f"(lo), "=f"(hi) : "l"(aJ0B3)); v0.w = lo + hi;
            asm("mov.b64 {%0,%1},%2;" : "=f"(lo), "=f"(hi) : "l"(aJ1B0)); v1.x = lo + hi;
            asm("mov.b64 {%0,%1},%2;" : "=f"(lo), "=f"(hi) : "l"(aJ1B1)); v1.y = lo + hi;
            asm("mov.b64 {%0,%1},%2;" : "=f"(lo), "=f"(hi) : "l"(aJ1B2)); v1.z = lo + hi;
            asm("mov.b64 {%0,%1},%2;" : "=f"(lo), "=f"(hi) : "l"(aJ1B3)); v1.w = lo + hi;
            float4* rp = (float4*)(redp + ((ks*3 + gate)*64 + 2*jl2)*4);
            rp[0] = v0;
            rp[1] = v1;
        }
        __syncthreads();

        // ---- epilogue: thread = (jl, b), tid<256; store hnew LOCALLY only
        if (tid < 256){
            float sr = 0.f, sz = 0.f, sn = 0.f;
            #pragma unroll
            for (int kq = 0; kq < 4; kq++){
                sr += redp[((kq*3 + 0)*64 + jl)*4 + b];
                sz += redp[((kq*3 + 1)*64 + jl)*4 + b];
                sn += redp[((kq*3 + 2)*64 + jl)*4 + b];
            }
            const float r = __fdividef(1.f, 1.f + __expf(-(xr + sr + br)));
            const float z = __fdividef(1.f, 1.f + __expf(-(xz + sz + bz)));
            const float targ = xn + r * (sn + bn);
            const float nn = 1.f - __fdividef(2.f, __expf(2.f*targ) + 1.f);
            const float hnew = (1.f - z) * nn + z * hprev;

            asm volatile("st.shared.f32 [%0],%1;"
                         :: "r"(hsN_u + (unsigned)(hEidx*4)), "f"(hnew) : "memory");
            g_io[((size_t)ta*Bx + bglob)*DHx + dir*Hx + jglob] = hnew;
            if (t == Sx - 1)
                hn_out[(size_t)dir*Bx*Hx + (size_t)bglob*Hx + jglob] = hnew;
        }
        __syncthreads();

        // ---- vectorized DSMEM push: own 1KB region -> 3 remote ranks (16B chunks)
        if (t < Sx - 1){
            if (tid < 192){
                const unsigned off = hsN_u + (unsigned)(q*1024 + pchnk*16);
                ull v0, v1;
                asm volatile("ld.shared.v2.u64 {%0,%1},[%2];"
                             : "=l"(v0), "=l"(v1) : "r"(off));
                asm volatile(
                    "{ .reg .b32 ra;\n\t"
                    "mapa.shared::cluster.u32 ra, %0, %1;\n\t"
                    "st.shared::cluster.v2.b64 [ra], {%2,%3}; }"
                    :: "r"(off), "r"(prk), "l"(v0), "l"(v1) : "memory");
            }
            asm volatile("barrier.cluster.arrive.aligned;" ::: "memory");
        }
        cur ^= 1;
    }
}

// =================================================================================
extern "C" void kernel_launch(void* const* d_in, const int* in_sizes, int n_in,
                              void* d_out, int out_size)
{
    const float* x     = (const float*)d_in[0];   // (512,64,128)
    const float* h0    = (const float*)d_in[1];   // (12,64,256)
    const float* w_ih0 = (const float*)d_in[2];   // (2,768,128)
    const float* w_ih  = (const float*)d_in[3];   // (5,2,768,512)
    const float* w_hh  = (const float*)d_in[4];   // (6,2,768,256)
    const float* b_ih  = (const float*)d_in[5];   // (6,2,768)
    const float* b_hh  = (const float*)d_in[6];   // (6,2,768)
    float* out = (float*)d_out;                   // (12,64,256)

    cudaFuncSetAttribute(gru_layer, cudaFuncAttributeMaxDynamicSharedMemorySize, SMEM_GRU);

    for (int layer = 0; layer < Lx; layer++){
        dim3 gg(G3/128, M_TOT/128, 2);
        if (layer == 0){
            gatex_gemm<128><<<gg, 256>>>(x, w_ih0, b_ih);
        } else {
            gatex_gemm<512><<<gg, 256>>>(
                x,
                w_ih + (size_t)(layer-1) * 2 * G3 * 512,
                b_ih + (size_t)layer * 2 * G3);
        }
        gru_layer<<<128, 384, SMEM_GRU>>>(
            h0   + (size_t)layer * 2 * Bx * Hx,
            w_hh + (size_t)layer * 2 * G3 * Hx,
            b_hh + (size_t)layer * 2 * G3,
            out  + (size_t)layer * 2 * Bx * Hx);
    }
}

// round 16
// speedup vs baseline: 1.3004x; 1.0909x over previous
#include <cuda_runtime.h>
#include <cstdint>
#include <math.h>

#define Sx 512
#define Bx 64
#define Hx 256
#define Lx 6
#define G3 768          // 3*H
#define DHx 512         // 2*H
#define M_TOT (Sx*Bx)   // 32768

typedef unsigned long long ull;

// ---------------- device scratch (static: no allocation allowed) ----------------
__device__ float g_gxT[2][(size_t)Sx*G3*Bx];   // [dir][s][gate*256+j][b] (bias added)
__device__ float g_io[(size_t)Sx*Bx*DHx];      // layer input/output (S,B,2H)

__device__ __forceinline__ unsigned f2tf32(float f){
    unsigned u;
    asm("cvt.rna.tf32.f32 %0,%1;" : "=r"(u) : "f"(f));
    return u;
}
__device__ __forceinline__ unsigned ctarank(){
    unsigned r; asm("mov.u32 %0, %%cluster_ctarank;" : "=r"(r)); return r;
}

// =================================================================================
// gate_x GEMM, tf32 tensor cores: block 128x128, BK=16, 8 warps, warp tile 64x32.
// DOUBLE-BUFFERED smem stages (1 syncthreads/tile) + register prefetch.
// Writes transposed gxT with bias added.
// =================================================================================
template<int K>
__global__ void __launch_bounds__(256,2) gatex_gemm(
    const float* __restrict__ xin,
    const float* __restrict__ Wbase,   // [2][768][K]
    const float* __restrict__ bias)    // [2][768]
{
    __shared__ unsigned As[2][16][136];
    __shared__ unsigned Bs[2][16][136];

    const int dir = blockIdx.z;
    const float* A = (K == 128) ? xin : g_io;
    const float* W = Wbase + (size_t)dir * G3 * K;
    const int n0 = blockIdx.x * 128;
    const int m0 = blockIdx.y * 128;
    const int tid = threadIdx.x;
    const int row  = tid >> 1;
    const int part = tid & 1;
    const int lane = tid & 31;
    const int w    = tid >> 5;
    const int wm = (w & 1) * 64;
    const int wn = (w >> 1) * 32;
    const int g = lane >> 2;
    const int t = lane & 3;
    const int k0 = part * 4;

    float acc[4][4][4];
    #pragma unroll
    for (int mt = 0; mt < 4; mt++)
        #pragma unroll
        for (int nt = 0; nt < 4; nt++)
            #pragma unroll
            for (int i = 0; i < 4; i++) acc[mt][nt][i] = 0.f;

    const float* Ald = A + (size_t)(m0 + row) * K + part * 4;
    const float* Wld = W + (size_t)(n0 + row) * K + part * 4;

    float4 av0 = *(const float4*)(Ald);
    float4 av1 = *(const float4*)(Ald + 8);
    float4 wv0 = *(const float4*)(Wld);
    float4 wv1 = *(const float4*)(Wld + 8);

    #define STAGE_STORE(S)                                                        \
    do {                                                                          \
        As[S][k0+0][row] = f2tf32(av0.x); As[S][k0+1][row] = f2tf32(av0.y);       \
        As[S][k0+2][row] = f2tf32(av0.z); As[S][k0+3][row] = f2tf32(av0.w);       \
        As[S][k0+8][row] = f2tf32(av1.x); As[S][k0+9][row] = f2tf32(av1.y);       \
        As[S][k0+10][row] = f2tf32(av1.z); As[S][k0+11][row] = f2tf32(av1.w);     \
        Bs[S][k0+0][row] = f2tf32(wv0.x); Bs[S][k0+1][row] = f2tf32(wv0.y);       \
        Bs[S][k0+2][row] = f2tf32(wv0.z); Bs[S][k0+3][row] = f2tf32(wv0.w);       \
        Bs[S][k0+8][row] = f2tf32(wv1.x); Bs[S][k0+9][row] = f2tf32(wv1.y);       \
        Bs[S][k0+10][row] = f2tf32(wv1.z); Bs[S][k0+11][row] = f2tf32(wv1.w);     \
    } while (0)

    STAGE_STORE(0);
    __syncthreads();

    int st = 0;
    for (int kt = 0; kt < K; kt += 16){
        const bool more = (kt + 16 < K);
        if (more){
            av0 = *(const float4*)(Ald + kt + 16);
            av1 = *(const float4*)(Ald + kt + 24);
            wv0 = *(const float4*)(Wld + kt + 16);
            wv1 = *(const float4*)(Wld + kt + 24);
        }
        #pragma unroll
        for (int c = 0; c < 2; c++){
            unsigned af[4][4], bf[4][2];
            #pragma unroll
            for (int mt = 0; mt < 4; mt++){
                const int m = wm + mt*16 + g;
                af[mt][0] = As[st][c*8 + t][m];
                af[mt][1] = As[st][c*8 + t][m + 8];
                af[mt][2] = As[st][c*8 + t + 4][m];
                af[mt][3] = As[st][c*8 + t + 4][m + 8];
            }
            #pragma unroll
            for (int nt = 0; nt < 4; nt++){
                const int n = wn + nt*8 + g;
                bf[nt][0] = Bs[st][c*8 + t][n];
                bf[nt][1] = Bs[st][c*8 + t + 4][n];
            }
            #pragma unroll
            for (int mt = 0; mt < 4; mt++)
                #pragma unroll
                for (int nt = 0; nt < 4; nt++)
                    asm volatile(
                        "mma.sync.aligned.m16n8k8.row.col.f32.tf32.tf32.f32 "
                        "{%0,%1,%2,%3},{%4,%5,%6,%7},{%8,%9},{%0,%1,%2,%3};"
                        : "+f"(acc[mt][nt][0]), "+f"(acc[mt][nt][1]),
                          "+f"(acc[mt][nt][2]), "+f"(acc[mt][nt][3])
                        : "r"(af[mt][0]), "r"(af[mt][1]), "r"(af[mt][2]), "r"(af[mt][3]),
                          "r"(bf[nt][0]), "r"(bf[nt][1]));
        }
        if (more){
            if (st) STAGE_STORE(0); else STAGE_STORE(1);
        }
        __syncthreads();
        st ^= 1;
    }
    #undef STAGE_STORE

    float* out = g_gxT[dir];
    const float* bs = bias + dir * G3;
    #pragma unroll
    for (int mt = 0; mt < 4; mt++){
        #pragma unroll
        for (int nt = 0; nt < 4; nt++){
            const int mr = m0 + wm + mt*16 + g;
            const int nc = n0 + wn + nt*8 + 2*t;
            const float b0 = bs[nc], b1 = bs[nc + 1];
            {
                const int s = mr >> 6, b = mr & 63;
                out[((size_t)s*G3 + nc    )*Bx + b] = acc[mt][nt][0] + b0;
                out[((size_t)s*G3 + nc + 1)*Bx + b] = acc[mt][nt][1] + b1;
            }
            {
                const int m2 = mr + 8;
                const int s = m2 >> 6, b = m2 & 63;
                out[((size_t)s*G3 + nc    )*Bx + b] = acc[mt][nt][2] + b0;
                out[((size_t)s*G3 + nc + 1)*Bx + b] = acc[mt][nt][3] + b1;
            }
        }
    }
}

// =================================================================================
// Cluster GRU layer (R13 + own-quarter compute BEFORE the cluster wait):
// grid 128 = 32 clusters x 4 CTAs, 384 threads. Own j-quarter of h(t) is written
// locally at t-1, so its 8 k2-iters/thread run before barrier.cluster.wait;
// the 24 remote-quarter iters run after. Vectorized DSMEM push unchanged.
// =================================================================================
#define WS_BYTES (96*129*16)                 // 198,144
#define HS_BYTES 4096
#define RED_OFF  (WS_BYTES + 2*HS_BYTES)     // 206,336
#define SMEM_GRU (RED_OFF + 12288)           // 218,624

__global__ void __launch_bounds__(384,1) __cluster_dims__(4,1,1)
gru_layer(
    const float* __restrict__ h0_l,    // [2][B][H]
    const float* __restrict__ whh_l,   // [2][768][256]
    const float* __restrict__ bhh_l,   // [2][768]
    float* __restrict__ hn_out)        // [2][B][H] slice of d_out
{
    extern __shared__ __align__(16) float smem[];
    const unsigned sb = (unsigned)__cvta_generic_to_shared(smem);

    const int cid  = blockIdx.x >> 2;   // cluster id 0..31
    const int q    = (int)ctarank();    // j-quarter 0..3
    const int dir  = cid >> 4;
    const int bgrp = cid & 15;
    const int tid  = threadIdx.x;

    // compute-phase mapping
    const int ks   = tid / 96;          // 0..3 (k-subslice within each quarter)
    const int rem  = tid - ks*96;
    const int gate = rem >> 5;          // 0..2
    const int jl2  = rem & 31;          // j-pair index

    // epilogue mapping (tid<256)
    const int jl = tid >> 2;            // 0..63
    const int b  = tid & 3;
    const int jglob = q*64 + jl;
    const int bglob = bgrp*4 + b;

    // push mapping (tid<192): 3 remote ranks x 64 16B-chunks of own 1KB region
    const int prk   = (q + 1 + (tid >> 6)) & 3;
    const int pchnk = tid & 63;

    // ---- stage W interleaved: ws[(gate*32+jl2)*129 + k2][4] = {j0e0,j0e1,j1e0,j1e1}
    for (int i = tid; i < 49152; i += 384){
        const int f = i & 3, jsel = f >> 1, e = f & 1;
        const int k2 = (i >> 2) & 127;
        const int rw = i >> 9;                 // 0..95
        const int gg = rw >> 5, jj2 = rw & 31;
        const int jloc = 2*jj2 + jsel;
        smem[((gg*32 + jj2)*129 + k2)*4 + f] =
            whh_l[((size_t)dir*G3 + gg*Hx + q*64 + jloc)*Hx + 2*k2 + e];
    }

    // ---- stage h0 into hsA: [k2][b][e], full 256 j, own 4 batches
    float* hsA = smem + WS_BYTES/4;
    for (int i = tid; i < 1024; i += 384){
        const int j = i >> 2, bb = i & 3;
        hsA[(j >> 1)*8 + bb*2 + (j & 1)] =
            h0_l[(size_t)dir*Bx*Hx + (size_t)(bgrp*4 + bb)*Hx + j];
    }

    // epilogue biases
    float br = 0.f, bz = 0.f, bn = 0.f;
    if (tid < 256){
        br = bhh_l[dir*G3 + jglob];
        bz = bhh_l[dir*G3 + Hx + jglob];
        bn = bhh_l[dir*G3 + 2*Hx + jglob];
    }
    __syncthreads();

    const unsigned wrow = sb + (unsigned)(((gate*32 + jl2)*129)*16);
    float* redp = smem + RED_OFF/4;
    const float* gxb = g_gxT[dir];
    const int hEidx = (jglob >> 1)*8 + b*2 + (jglob & 1);

    int cur = 0;
    for (int t = 0; t < Sx; t++){
        const int ta = dir ? (Sx - 1 - t) : t;
        const unsigned hsC_u = sb + WS_BYTES + (unsigned)cur*HS_BYTES;
        const unsigned hsN_u = sb + WS_BYTES + (unsigned)(cur ^ 1)*HS_BYTES;

        // ---- prefetch gate_x + local hprev (own quarter: valid before the wait)
        float xr = 0.f, xz = 0.f, xn = 0.f, hprev = 0.f;
        if (tid < 256){
            const float* p = gxb + (size_t)ta*G3*Bx + bglob;
            xr = __ldg(p + (size_t)(0*Hx + jglob)*Bx);
            xz = __ldg(p + (size_t)(1*Hx + jglob)*Bx);
            xn = __ldg(p + (size_t)(2*Hx + jglob)*Bx);
            asm volatile("ld.shared.f32 %0,[%1];"
                         : "=f"(hprev) : "r"(hsC_u + (unsigned)(hEidx*4)));
        }

        ull aJ0B0=0, aJ0B1=0, aJ0B2=0, aJ0B3=0, aJ1B0=0, aJ1B1=0, aJ1B2=0, aJ1B3=0;

        #define DOT8(K2BASE)                                                          \
        do {                                                                          \
            const unsigned wA = wrow + (unsigned)((K2BASE)*16);                       \
            const unsigned hA = hsC_u + (unsigned)((K2BASE)*32);                      \
            _Pragma("unroll")                                                         \
            for (int k = 0; k < 8; k++){                                              \
                ull wj0, wj1, hb0, hb1, hb2, hb3;                                     \
                asm volatile("ld.shared.v2.u64 {%0,%1},[%2];"                         \
                             : "=l"(wj0), "=l"(wj1) : "r"(wA + k*16));                \
                asm volatile("ld.shared.v2.u64 {%0,%1},[%2];"                         \
                             : "=l"(hb0), "=l"(hb1) : "r"(hA + k*32));                \
                asm volatile("ld.shared.v2.u64 {%0,%1},[%2];"                         \
                             : "=l"(hb2), "=l"(hb3) : "r"(hA + k*32 + 16));           \
                asm("fma.rn.f32x2 %0,%1,%2,%0;" : "+l"(aJ0B0) : "l"(wj0), "l"(hb0));  \
                asm("fma.rn.f32x2 %0,%1,%2,%0;" : "+l"(aJ0B1) : "l"(wj0), "l"(hb1));  \
                asm("fma.rn.f32x2 %0,%1,%2,%0;" : "+l"(aJ0B2) : "l"(wj0), "l"(hb2));  \
                asm("fma.rn.f32x2 %0,%1,%2,%0;" : "+l"(aJ0B3) : "l"(wj0), "l"(hb3));  \
                asm("fma.rn.f32x2 %0,%1,%2,%0;" : "+l"(aJ1B0) : "l"(wj1), "l"(hb0));  \
                asm("fma.rn.f32x2 %0,%1,%2,%0;" : "+l"(aJ1B1) : "l"(wj1), "l"(hb1));  \
                asm("fma.rn.f32x2 %0,%1,%2,%0;" : "+l"(aJ1B2) : "l"(wj1), "l"(hb2));  \
                asm("fma.rn.f32x2 %0,%1,%2,%0;" : "+l"(aJ1B3) : "l"(wj1), "l"(hb3));  \
            }                                                                         \
        } while (0)

        // ---- own quarter FIRST (locally written at t-1; no barrier needed)
        DOT8(q*32 + ks*8);

        // ---- wait for previous step's remote DSMEM pushes
        if (t > 0)
            asm volatile("barrier.cluster.wait.aligned;" ::: "memory");

        // ---- remaining 3 quarters
        #pragma unroll
        for (int qq = 1; qq < 4; qq++){
            const int d = (q + qq) & 3;
            DOT8(d*32 + ks*8);
        }
        #undef DOT8

        // collapse k-parity, publish partials: red[(ks*3+gate)*64 + j][b]
        {
            float4 v0, v1; float lo, hi;
            asm("mov.b64 {%0,%1},%2;" : "=f"(lo), "=f"(hi) : "l"(aJ0B0)); v0.x = lo + hi;
            asm("mov.b64 {%0,%1},%2;" : "=f"(lo), "=f"(hi) : "l"(aJ0B1)); v0.y = lo + hi;
            asm("mov.b64 {%0,%1},%2;" : "=f"(lo), "=f"(hi) : "l"(aJ0B2)); v0.z = lo + hi;
            asm("mov.b64 {%0,%1},%2;" : "=f"(lo), "=f"(hi) : "l"(aJ0B3)); v0.w = lo + hi;
            asm("mov.b64 {%0,%1},%2;" : "=f"(lo), "=f"(hi) : "l"(aJ1B0)); v1.x = lo + hi;
            asm("mov.b64 {%0,%1},%2;" : "=f"(lo), "=f"(hi) : "l"(aJ1B1)); v1.y = lo + hi;
            asm("mov.b64 {%0,%1},%2;" : "=f"(lo), "=f"(hi) : "l"(aJ1B2)); v1.z = lo + hi;
            asm("mov.b64 {%0,%1},%2;" : "=f"(lo), "=f"(hi) : "l"(aJ1B3)); v1.w = lo + hi;
            float4* rp = (float4*)(redp + ((ks*3 + gate)*64 + 2*jl2)*4);
            rp[0] = v0;
            rp[1] = v1;
        }
        __syncthreads();

        // ---- epilogue: thread = (jl, b), tid<256; store hnew LOCALLY only
        if (tid < 256){
            float sr = 0.f, sz = 0.f, sn = 0.f;
            #pragma unroll
            for (int kq = 0; kq < 4; kq++){
                sr += redp[((kq*3 + 0)*64 + jl)*4 + b];
                sz += redp[((kq*3 + 1)*64 + jl)*4 + b];
                sn += redp[((kq*3 + 2)*64 + jl)*4 + b];
            }
            const float r = __fdividef(1.f, 1.f + __expf(-(xr + sr + br)));
            const float z = __fdividef(1.f, 1.f + __expf(-(xz + sz + bz)));
            const float targ = xn + r * (sn + bn);
            const float nn = 1.f - __fdividef(2.f, __expf(2.f*targ) + 1.f);
            const float hnew = (1.f - z) * nn + z * hprev;

            asm volatile("st.shared.f32 [%0],%1;"
                         :: "r"(hsN_u + (unsigned)(hEidx*4)), "f"(hnew) : "memory");
            g_io[((size_t)ta*Bx + bglob)*DHx + dir*Hx + jglob] = hnew;
            if (t == Sx - 1)
                hn_out[(size_t)dir*Bx*Hx + (size_t)bglob*Hx + jglob] = hnew;
        }
        __syncthreads();

        // ---- vectorized DSMEM push: own 1KB region -> 3 remote ranks (16B chunks)
        if (t < Sx - 1){
            if (tid < 192){
                const unsigned off = hsN_u + (unsigned)(q*1024 + pchnk*16);
                ull v0, v1;
                asm volatile("ld.shared.v2.u64 {%0,%1},[%2];"
                             : "=l"(v0), "=l"(v1) : "r"(off));
                asm volatile(
                    "{ .reg .b32 ra;\n\t"
                    "mapa.shared::cluster.u32 ra, %0, %1;\n\t"
                    "st.shared::cluster.v2.b64 [ra], {%2,%3}; }"
                    :: "r"(off), "r"(prk), "l"(v0), "l"(v1) : "memory");
            }
            asm volatile("barrier.cluster.arrive.aligned;" ::: "memory");
        }
        cur ^= 1;
    }
}

// =================================================================================
extern "C" void kernel_launch(void* const* d_in, const int* in_sizes, int n_in,
                              void* d_out, int out_size)
{
    const float* x     = (const float*)d_in[0];   // (512,64,128)
    const float* h0    = (const float*)d_in[1];   // (12,64,256)
    const float* w_ih0 = (const float*)d_in[2];   // (2,768,128)
    const float* w_ih  = (const float*)d_in[3];   // (5,2,768,512)
    const float* w_hh  = (const float*)d_in[4];   // (6,2,768,256)
    const float* b_ih  = (const float*)d_in[5];   // (6,2,768)
    const float* b_hh  = (const float*)d_in[6];   // (6,2,768)
    float* out = (float*)d_out;                   // (12,64,256)

    cudaFuncSetAttribute(gru_layer, cudaFuncAttributeMaxDynamicSharedMemorySize, SMEM_GRU);

    for (int layer = 0; layer < Lx; layer++){
        dim3 gg(G3/128, M_TOT/128, 2);
        if (layer == 0){
            gatex_gemm<128><<<gg, 256>>>(x, w_ih0, b_ih);
        } else {
            gatex_gemm<512><<<gg, 256>>>(
                x,
                w_ih + (size_t)(layer-1) * 2 * G3 * 512,
                b_ih + (size_t)layer * 2 * G3);
        }
        gru_layer<<<128, 384, SMEM_GRU>>>(
            h0   + (size_t)layer * 2 * Bx * Hx,
            w_hh + (size_t)layer * 2 * G3 * Hx,
            b_hh + (size_t)layer * 2 * G3,
            out  + (size_t)layer * 2 * Bx * Hx);
    }
}